// round 2
// baseline (speedup 1.0000x reference)
#include <cuda_runtime.h>
#include <cstdint>

namespace {

constexpr int kB = 64;
constexpr int kN = 8;
constexpr int kV = 128000;
constexpr int kCH = 8;                 // chunks per row
constexpr int kChunk = kV / kCH;       // 16000
constexpr int kTPB = 256;

__device__ int   g_em[kB];
__device__ float g_psum[kB * kCH];
__device__ float g_bval[kB * kCH];
__device__ int   g_bidx[kB * kCH];
__device__ float g_rval[kB * kCH];
__device__ int   g_ridx[kB * kCH];

__device__ __forceinline__ float neg_inf() { return __int_as_float(0xff800000); }

// ---------------- JAX threefry2x32 (exact round structure from jax/_src/prng.py) ----
__device__ __forceinline__ void tfround(uint32_t& x0, uint32_t& x1, int r) {
  x0 += x1;
  x1 = __funnelshift_l(x1, x1, r);   // rotate-left
  x1 ^= x0;
}

__device__ __forceinline__ uint2 threefry2x32(uint32_t k0, uint32_t k1,
                                              uint32_t x0, uint32_t x1) {
  uint32_t k2 = k0 ^ k1 ^ 0x1BD11BDAu;
  x0 += k0; x1 += k1;
  tfround(x0, x1, 13); tfround(x0, x1, 15); tfround(x0, x1, 26); tfround(x0, x1, 6);
  x0 += k1; x1 += k2 + 1u;
  tfround(x0, x1, 17); tfround(x0, x1, 29); tfround(x0, x1, 16); tfround(x0, x1, 24);
  x0 += k2; x1 += k0 + 2u;
  tfround(x0, x1, 13); tfround(x0, x1, 15); tfround(x0, x1, 26); tfround(x0, x1, 6);
  x0 += k0; x1 += k1 + 3u;
  tfround(x0, x1, 17); tfround(x0, x1, 29); tfround(x0, x1, 16); tfround(x0, x1, 24);
  x0 += k1; x1 += k2 + 4u;
  tfround(x0, x1, 13); tfround(x0, x1, 15); tfround(x0, x1, 26); tfround(x0, x1, 6);
  x0 += k2; x1 += k0 + 5u;
  return make_uint2(x0, x1);
}

// Partitionable random_bits: bits(L) = o0 ^ o1 of threefry(key, (hi(L)=0, lo(L)=L))
__device__ __forceinline__ uint32_t rbits32(uint2 key, uint32_t idx) {
  uint2 o = threefry2x32(key.x, key.y, 0u, idx);
  return o.x ^ o.y;
}

// uniform [0,1): bitcast((bits>>9)|0x3f800000) - 1
__device__ __forceinline__ float uni01(uint32_t bits) {
  return __uint_as_float((bits >> 9) | 0x3f800000u) - 1.0f;
}

// gumbel = -log(-log(uniform(minval=FLT_TINY, maxval=1)))
__device__ __forceinline__ float gumbel32(uint2 key, uint32_t idx) {
  float f = uni01(rbits32(key, idx));
  float u = fmaxf(f, 1.17549435e-38f);
  return -logf(-logf(u));
}

// ---------------- Kernel A: u, accept, accepted_num, emitted_num -------------------
__global__ void kSetup(const int* __restrict__ tok, const float* __restrict__ dp,
                       const float* __restrict__ vp, float* __restrict__ out,
                       int out_size) {
  int b = threadIdx.x;
  if (b >= kB) return;
  // ku = split(key(1), 3)[0]  (fold-like split: full threefry output pair)
  uint2 ku = threefry2x32(0u, 1u, 0u, 0u);
  bool acc_arr[kN];
#pragma unroll
  for (int n = 0; n < kN; n++) {
    int L = b * kN + n;
    float u = uni01(rbits32(ku, (uint32_t)L));
    int t = tok[L];
    t = min(max(t, 0), kV - 1);  // defensive clamp
    float q = dp[(size_t)L * kV + t];
    float p = vp[((size_t)b * (kN + 1) + n) * kV + t];
    acc_arr[n] = (u * q < p);
  }
  int acc = 0, em = 0;
  bool alive = true;
#pragma unroll
  for (int n = 0; n < kN; n++) {
    acc += acc_arr[n] ? 1 : 0;
    if (alive) { if (acc_arr[n]) em++; else alive = false; }
  }
  if (out_size >= kB * (kN + 1) + 2 * kB) {
    out[kB * (kN + 1) + b] = (float)acc;        // accepted_token_num
    out[kB * (kN + 1) + kB + b] = (float)em;    // emitted_token_num
  }
  g_em[b] = em;
}

// ---------------- Kernel B: bonus = categorical(kb, log(verify[:,N,:] + EPS)) ------
__global__ void kBonus(const float* __restrict__ vp) {
  int b = blockIdx.x >> 3;
  int c = blockIdx.x & (kCH - 1);
  int t = threadIdx.x;
  uint2 kb = threefry2x32(0u, 1u, 0u, 2u);  // subkey 2
  const float* row = vp + ((size_t)b * (kN + 1) + kN) * kV;
  uint32_t Lbase = (uint32_t)b * (uint32_t)kV;  // gumbel shape (B, V)
  float bestv = neg_inf();
  int besti = 0x7fffffff;
  for (int v = c * kChunk + t; v < (c + 1) * kChunk; v += kTPB) {
    float val = logf(row[v] + 1e-20f) + gumbel32(kb, Lbase + (uint32_t)v);
    if (val > bestv) { bestv = val; besti = v; }
  }
  __shared__ float sv[kTPB];
  __shared__ int   si[kTPB];
  sv[t] = bestv; si[t] = besti;
  __syncthreads();
  for (int s = kTPB / 2; s > 0; s >>= 1) {
    if (t < s) {
      float v2 = sv[t + s]; int i2 = si[t + s];
      if (v2 > sv[t] || (v2 == sv[t] && i2 < si[t])) { sv[t] = v2; si[t] = i2; }
    }
    __syncthreads();
  }
  if (t == 0) { g_bval[blockIdx.x] = sv[0]; g_bidx[blockIdx.x] = si[0]; }
}

// ---------------- Kernel C1: partial sums of residual for the selected row --------
__global__ void kResidSum(const float* __restrict__ dp, const float* __restrict__ vp) {
  int b = blockIdx.x >> 3;
  int c = blockIdx.x & (kCH - 1);
  int t = threadIdx.x;
  int em = g_em[b];
  if (em >= kN) { if (t == 0) g_psum[blockIdx.x] = 0.0f; return; }
  const float* drow = dp + ((size_t)b * kN + em) * kV;
  const float* vrow = vp + ((size_t)b * (kN + 1) + em) * kV;
  float s = 0.0f;
  for (int v = c * kChunk + t; v < (c + 1) * kChunk; v += kTPB)
    s += fmaxf(vrow[v] - drow[v], 0.0f);
  __shared__ float sm[kTPB];
  sm[t] = s;
  __syncthreads();
  for (int st = kTPB / 2; st > 0; st >>= 1) {
    if (t < st) sm[t] += sm[t + st];
    __syncthreads();
  }
  if (t == 0) g_psum[blockIdx.x] = sm[0];
}

// ---------------- Kernel C2: recovered = categorical(kr, log(residual/S' + EPS)) ---
__global__ void kRecover(const float* __restrict__ dp, const float* __restrict__ vp) {
  int b = blockIdx.x >> 3;
  int c = blockIdx.x & (kCH - 1);
  int t = threadIdx.x;
  int em = g_em[b];
  if (em >= kN) {
    if (t == 0) { g_rval[blockIdx.x] = neg_inf(); g_ridx[blockIdx.x] = 0; }
    return;
  }
  float S = 0.0f;
#pragma unroll
  for (int i = 0; i < kCH; i++) S += g_psum[b * kCH + i];
  float Sp = fmaxf(S, 1e-20f);
  uint2 kr = threefry2x32(0u, 1u, 0u, 1u);  // subkey 1
  const float* drow = dp + ((size_t)b * kN + em) * kV;
  const float* vrow = vp + ((size_t)b * (kN + 1) + em) * kV;
  uint32_t Lbase = (uint32_t)(b * kN + em) * (uint32_t)kV;  // gumbel shape (B, N, V)
  float bestv = neg_inf();
  int besti = 0x7fffffff;
  for (int v = c * kChunk + t; v < (c + 1) * kChunk; v += kTPB) {
    float r = fmaxf(vrow[v] - drow[v], 0.0f);
    float lg = logf(__fdiv_rn(r, Sp) + 1e-20f);
    float val = lg + gumbel32(kr, Lbase + (uint32_t)v);
    if (val > bestv) { bestv = val; besti = v; }
  }
  __shared__ float sv[kTPB];
  __shared__ int   si[kTPB];
  sv[t] = bestv; si[t] = besti;
  __syncthreads();
  for (int s = kTPB / 2; s > 0; s >>= 1) {
    if (t < s) {
      float v2 = sv[t + s]; int i2 = si[t + s];
      if (v2 > sv[t] || (v2 == sv[t] && i2 < si[t])) { sv[t] = v2; si[t] = i2; }
    }
    __syncthreads();
  }
  if (t == 0) { g_rval[blockIdx.x] = sv[0]; g_ridx[blockIdx.x] = si[0]; }
}

// ---------------- Kernel D: combine partials, assemble output ----------------------
__global__ void kFinal(const int* __restrict__ tok, float* __restrict__ out) {
  int b = threadIdx.x;
  if (b >= kB) return;
  float bv = neg_inf(); int bi = 0x7fffffff;
#pragma unroll
  for (int c = 0; c < kCH; c++) {
    float v = g_bval[b * kCH + c]; int i = g_bidx[b * kCH + c];
    if (v > bv || (v == bv && i < bi)) { bv = v; bi = i; }
  }
  int em = g_em[b];
  int fin = bi;  // bonus when em == N
  if (em < kN) {
    float rv = neg_inf(); int ri = 0x7fffffff;
#pragma unroll
    for (int c = 0; c < kCH; c++) {
      float v = g_rval[b * kCH + c]; int i = g_ridx[b * kCH + c];
      if (v > rv || (v == rv && i < ri)) { rv = v; ri = i; }
    }
    fin = ri;
  }
#pragma unroll
  for (int pos = 0; pos < kN + 1; pos++) {
    float o;
    if (pos < em)       o = (float)tok[b * kN + pos];
    else if (pos == em) o = (float)fin;
    else                o = -1.0f;
    out[b * (kN + 1) + pos] = o;
  }
}

}  // namespace

extern "C" void kernel_launch(void* const* d_in, const int* in_sizes, int n_in,
                              void* d_out, int out_size) {
  // Identify inputs by element count (robust to metadata ordering):
  //   draft_token_ids: 64*8          = 512
  //   draft_probs:     64*8*128000   = 65,536,000
  //   verify_probs:    64*9*128000   = 73,728,000
  const int*   tok = nullptr;
  const float* dp  = nullptr;
  const float* vp  = nullptr;
  for (int i = 0; i < n_in; i++) {
    if (in_sizes[i] == kB * kN)                      tok = (const int*)d_in[i];
    else if (in_sizes[i] == kB * kN * kV)            dp  = (const float*)d_in[i];
    else if (in_sizes[i] == kB * (kN + 1) * kV)      vp  = (const float*)d_in[i];
  }
  float* out = (float*)d_out;

  kSetup<<<1, kB>>>(tok, dp, vp, out, out_size);
  kBonus<<<kB * kCH, kTPB>>>(vp);
  kResidSum<<<kB * kCH, kTPB>>>(dp, vp);
  kRecover<<<kB * kCH, kTPB>>>(dp, vp);
  kFinal<<<1, kB>>>(tok, out);
}

// round 3
// speedup vs baseline: 1.0014x; 1.0014x over previous
#include <cuda_runtime.h>
#include <cstdint>

namespace {

constexpr int kB = 64;
constexpr int kN = 8;
constexpr int kV = 128000;
constexpr int kCH = 8;                 // chunks per row
constexpr int kQ4 = kV / kCH / 4;      // float4s per chunk = 4000
constexpr int kTPB = 256;

__device__ int   g_em[kB];
__device__ float g_psum[kB * kCH];
__device__ float g_bval[kB * kCH];
__device__ int   g_bidx[kB * kCH];
__device__ float g_rval[kB * kCH];
__device__ int   g_ridx[kB * kCH];

__device__ __forceinline__ float neg_inf() { return __int_as_float(0xff800000); }

// ---------------- JAX threefry2x32 (exact round structure) -------------------------
__device__ __forceinline__ void tfround(uint32_t& x0, uint32_t& x1, int r) {
  x0 += x1;
  x1 = __funnelshift_l(x1, x1, r);
  x1 ^= x0;
}

__device__ __forceinline__ uint2 threefry2x32(uint32_t k0, uint32_t k1,
                                              uint32_t x0, uint32_t x1) {
  uint32_t k2 = k0 ^ k1 ^ 0x1BD11BDAu;
  x0 += k0; x1 += k1;
  tfround(x0, x1, 13); tfround(x0, x1, 15); tfround(x0, x1, 26); tfround(x0, x1, 6);
  x0 += k1; x1 += k2 + 1u;
  tfround(x0, x1, 17); tfround(x0, x1, 29); tfround(x0, x1, 16); tfround(x0, x1, 24);
  x0 += k2; x1 += k0 + 2u;
  tfround(x0, x1, 13); tfround(x0, x1, 15); tfround(x0, x1, 26); tfround(x0, x1, 6);
  x0 += k0; x1 += k1 + 3u;
  tfround(x0, x1, 17); tfround(x0, x1, 29); tfround(x0, x1, 16); tfround(x0, x1, 24);
  x0 += k1; x1 += k2 + 4u;
  tfround(x0, x1, 13); tfround(x0, x1, 15); tfround(x0, x1, 26); tfround(x0, x1, 6);
  x0 += k2; x1 += k0 + 5u;
  return make_uint2(x0, x1);
}

__device__ __forceinline__ uint32_t rbits32(uint2 key, uint32_t idx) {
  uint2 o = threefry2x32(key.x, key.y, 0u, idx);
  return o.x ^ o.y;
}

__device__ __forceinline__ float uni01(uint32_t bits) {
  return __uint_as_float((bits >> 9) | 0x3f800000u) - 1.0f;
}

// gumbel = -log(-log(max(u, tiny))). Inner log accurate (error amplified 1/t near
// u~1 — argmax candidates live there); outer log fast (bounded abs err ~4e-6).
__device__ __forceinline__ float gumbel32(uint2 key, uint32_t idx) {
  float f = uni01(rbits32(key, idx));
  float u = fmaxf(f, 1.17549435e-38f);
  float t = -logf(u);          // accurate
  return -__logf(t);           // fast
}

struct BestPair { float v; int i; };

__device__ __forceinline__ void upd(BestPair& b, float v, int i) {
  if (v > b.v) { b.v = v; b.i = i; }
}

__device__ __forceinline__ void block_argmax_out(BestPair best, float* gv, int* gi) {
  __shared__ float sv[kTPB];
  __shared__ int   si[kTPB];
  int t = threadIdx.x;
  sv[t] = best.v; si[t] = best.i;
  __syncthreads();
  for (int s = kTPB / 2; s > 0; s >>= 1) {
    if (t < s) {
      float v2 = sv[t + s]; int i2 = si[t + s];
      if (v2 > sv[t] || (v2 == sv[t] && i2 < si[t])) { sv[t] = v2; si[t] = i2; }
    }
    __syncthreads();
  }
  if (t == 0) { *gv = sv[0]; *gi = si[0]; }
}

// ---------------- Kernel A: accept / accepted_num / emitted_num --------------------
__global__ void kSetup(const int* __restrict__ tok, const float* __restrict__ dp,
                       const float* __restrict__ vp, float* __restrict__ out,
                       int out_size) {
  int b = threadIdx.x;
  if (b >= kB) return;
  uint2 ku = threefry2x32(0u, 1u, 0u, 0u);   // split(key(1),3)[0]
  bool acc_arr[kN];
#pragma unroll
  for (int n = 0; n < kN; n++) {
    int L = b * kN + n;
    float u = uni01(rbits32(ku, (uint32_t)L));
    int t = tok[L];
    t = min(max(t, 0), kV - 1);
    float q = dp[(size_t)L * kV + t];
    float p = vp[((size_t)b * (kN + 1) + n) * kV + t];
    acc_arr[n] = (u * q < p);
  }
  int acc = 0, em = 0;
  bool alive = true;
#pragma unroll
  for (int n = 0; n < kN; n++) {
    acc += acc_arr[n] ? 1 : 0;
    if (alive) { if (acc_arr[n]) em++; else alive = false; }
  }
  if (out_size >= kB * (kN + 1) + 2 * kB) {
    out[kB * (kN + 1) + b] = (float)acc;
    out[kB * (kN + 1) + kB + b] = (float)em;
  }
  g_em[b] = em;
}

// ---------------- Kernel C1: residual partial sums (vectorized) --------------------
__global__ void kResidSum(const float* __restrict__ dp, const float* __restrict__ vp) {
  int b = blockIdx.x >> 3;
  int c = blockIdx.x & (kCH - 1);
  int t = threadIdx.x;
  int em = g_em[b];
  if (em >= kN) { if (t == 0) g_psum[blockIdx.x] = 0.0f; return; }
  const float4* drow = (const float4*)(dp + ((size_t)b * kN + em) * kV);
  const float4* vrow = (const float4*)(vp + ((size_t)b * (kN + 1) + em) * kV);
  float s = 0.0f;
  for (int i = c * kQ4 + t; i < (c + 1) * kQ4; i += kTPB) {
    float4 d4 = drow[i];
    float4 v4 = vrow[i];
    s += fmaxf(v4.x - d4.x, 0.0f) + fmaxf(v4.y - d4.y, 0.0f)
       + fmaxf(v4.z - d4.z, 0.0f) + fmaxf(v4.w - d4.w, 0.0f);
  }
  __shared__ float sm[kTPB];
  sm[t] = s;
  __syncthreads();
  for (int st = kTPB / 2; st > 0; st >>= 1) {
    if (t < st) sm[t] += sm[t + st];
    __syncthreads();
  }
  if (t == 0) g_psum[blockIdx.x] = sm[0];
}

// ---------------- Kernel F: fused bonus + recovered gumbel-argmax ------------------
// blocks [0, 512):    bonus    (b = blk>>3, chunk = blk&7)
// blocks [512, 1024): recover
__global__ void kGumbel(const float* __restrict__ dp, const float* __restrict__ vp) {
  int blk = blockIdx.x;
  bool is_bonus = blk < kB * kCH;
  int rb = is_bonus ? blk : blk - kB * kCH;
  int b = rb >> 3;
  int c = rb & (kCH - 1);
  int t = threadIdx.x;

  BestPair best = {neg_inf(), 0x7fffffff};

  if (is_bonus) {
    uint2 kb = threefry2x32(0u, 1u, 0u, 2u);  // subkey 2
    const float4* row = (const float4*)(vp + ((size_t)b * (kN + 1) + kN) * kV);
    uint32_t Lbase = (uint32_t)b * (uint32_t)kV;   // gumbel shape (B, V)
    for (int i = c * kQ4 + t; i < (c + 1) * kQ4; i += kTPB) {
      float4 p4 = row[i];
      int v = 4 * i;
      upd(best, __logf(p4.x + 1e-20f) + gumbel32(kb, Lbase + v + 0), v + 0);
      upd(best, __logf(p4.y + 1e-20f) + gumbel32(kb, Lbase + v + 1), v + 1);
      upd(best, __logf(p4.z + 1e-20f) + gumbel32(kb, Lbase + v + 2), v + 2);
      upd(best, __logf(p4.w + 1e-20f) + gumbel32(kb, Lbase + v + 3), v + 3);
    }
    block_argmax_out(best, &g_bval[rb], &g_bidx[rb]);
  } else {
    int em = g_em[b];
    if (em >= kN) {
      if (t == 0) { g_rval[rb] = neg_inf(); g_ridx[rb] = 0; }
      return;
    }
    float S = 0.0f;
#pragma unroll
    for (int i = 0; i < kCH; i++) S += g_psum[b * kCH + i];
    float Sp = fmaxf(S, 1e-20f);
    float invSp_unused = 0.0f; (void)invSp_unused;
    uint2 kr = threefry2x32(0u, 1u, 0u, 1u);  // subkey 1
    const float4* drow = (const float4*)(dp + ((size_t)b * kN + em) * kV);
    const float4* vrow = (const float4*)(vp + ((size_t)b * (kN + 1) + em) * kV);
    uint32_t Lbase = (uint32_t)(b * kN + em) * (uint32_t)kV;  // gumbel shape (B, N, V)
    for (int i = c * kQ4 + t; i < (c + 1) * kQ4; i += kTPB) {
      float4 d4 = drow[i];
      float4 v4 = vrow[i];
      int v = 4 * i;
      {
        float r = fmaxf(v4.x - d4.x, 0.0f);
        upd(best, __logf(__fdiv_rn(r, Sp) + 1e-20f) + gumbel32(kr, Lbase + v + 0), v + 0);
      }
      {
        float r = fmaxf(v4.y - d4.y, 0.0f);
        upd(best, __logf(__fdiv_rn(r, Sp) + 1e-20f) + gumbel32(kr, Lbase + v + 1), v + 1);
      }
      {
        float r = fmaxf(v4.z - d4.z, 0.0f);
        upd(best, __logf(__fdiv_rn(r, Sp) + 1e-20f) + gumbel32(kr, Lbase + v + 2), v + 2);
      }
      {
        float r = fmaxf(v4.w - d4.w, 0.0f);
        upd(best, __logf(__fdiv_rn(r, Sp) + 1e-20f) + gumbel32(kr, Lbase + v + 3), v + 3);
      }
    }
    block_argmax_out(best, &g_rval[rb], &g_ridx[rb]);
  }
}

// ---------------- Kernel D: combine partials, assemble output ----------------------
__global__ void kFinal(const int* __restrict__ tok, float* __restrict__ out) {
  int b = threadIdx.x;
  if (b >= kB) return;
  float bv = neg_inf(); int bi = 0x7fffffff;
#pragma unroll
  for (int c = 0; c < kCH; c++) {
    float v = g_bval[b * kCH + c]; int i = g_bidx[b * kCH + c];
    if (v > bv || (v == bv && i < bi)) { bv = v; bi = i; }
  }
  int em = g_em[b];
  int fin = bi;
  if (em < kN) {
    float rv = neg_inf(); int ri = 0x7fffffff;
#pragma unroll
    for (int c = 0; c < kCH; c++) {
      float v = g_rval[b * kCH + c]; int i = g_ridx[b * kCH + c];
      if (v > rv || (v == rv && i < ri)) { rv = v; ri = i; }
    }
    fin = ri;
  }
#pragma unroll
  for (int pos = 0; pos < kN + 1; pos++) {
    float o;
    if (pos < em)       o = (float)tok[b * kN + pos];
    else if (pos == em) o = (float)fin;
    else                o = -1.0f;
    out[b * (kN + 1) + pos] = o;
  }
}

}  // namespace

extern "C" void kernel_launch(void* const* d_in, const int* in_sizes, int n_in,
                              void* d_out, int out_size) {
  const int*   tok = nullptr;
  const float* dp  = nullptr;
  const float* vp  = nullptr;
  for (int i = 0; i < n_in; i++) {
    if (in_sizes[i] == kB * kN)                      tok = (const int*)d_in[i];
    else if (in_sizes[i] == kB * kN * kV)            dp  = (const float*)d_in[i];
    else if (in_sizes[i] == kB * (kN + 1) * kV)      vp  = (const float*)d_in[i];
  }
  float* out = (float*)d_out;

  kSetup<<<1, kB>>>(tok, dp, vp, out, out_size);
  kResidSum<<<kB * kCH, kTPB>>>(dp, vp);
  kGumbel<<<2 * kB * kCH, kTPB>>>(dp, vp);
  kFinal<<<1, kB>>>(tok, out);
}

// round 4
// speedup vs baseline: 2.0801x; 2.0772x over previous
#include <cuda_runtime.h>
#include <cstdint>

namespace {

constexpr int kB = 64;
constexpr int kN = 8;
constexpr int kV = 128000;
constexpr int kCH = 16;                 // chunks per row
constexpr int kQ4 = kV / kCH / 4;       // float4s per chunk = 2000
constexpr int kTPB = 128;
constexpr int kBonusBlocks = kB * kCH;        // 1024
constexpr int kGridTotal   = 2 * kB * kCH;    // 2048

__device__ int      g_em[kB];
__device__ float    g_bval[kB * kCH];
__device__ int      g_bidx[kB * kCH];
__device__ float    g_rval[kB * kCH];
__device__ int      g_ridx[kB * kCH];
__device__ unsigned g_ticket;

__device__ __forceinline__ float neg_inf() { return __int_as_float(0xff800000); }

// ---------------- JAX threefry2x32 (exact round structure) -------------------------
__device__ __forceinline__ void tfround(uint32_t& x0, uint32_t& x1, int r) {
  x0 += x1;
  x1 = __funnelshift_l(x1, x1, r);
  x1 ^= x0;
}

__device__ __forceinline__ uint2 threefry2x32(uint32_t k0, uint32_t k1,
                                              uint32_t x0, uint32_t x1) {
  uint32_t k2 = k0 ^ k1 ^ 0x1BD11BDAu;
  x0 += k0; x1 += k1;
  tfround(x0, x1, 13); tfround(x0, x1, 15); tfround(x0, x1, 26); tfround(x0, x1, 6);
  x0 += k1; x1 += k2 + 1u;
  tfround(x0, x1, 17); tfround(x0, x1, 29); tfround(x0, x1, 16); tfround(x0, x1, 24);
  x0 += k2; x1 += k0 + 2u;
  tfround(x0, x1, 13); tfround(x0, x1, 15); tfround(x0, x1, 26); tfround(x0, x1, 6);
  x0 += k0; x1 += k1 + 3u;
  tfround(x0, x1, 17); tfround(x0, x1, 29); tfround(x0, x1, 16); tfround(x0, x1, 24);
  x0 += k1; x1 += k2 + 4u;
  tfround(x0, x1, 13); tfround(x0, x1, 15); tfround(x0, x1, 26); tfround(x0, x1, 6);
  x0 += k2; x1 += k0 + 5u;
  return make_uint2(x0, x1);
}

__device__ __forceinline__ uint32_t rbits32(uint2 key, uint32_t idx) {
  uint2 o = threefry2x32(key.x, key.y, 0u, idx);
  return o.x ^ o.y;
}

__device__ __forceinline__ float uni01(uint32_t bits) {
  return __uint_as_float((bits >> 9) | 0x3f800000u) - 1.0f;
}

// gumbel = -log(-log(max(u, tiny))). Inner log accurate (winners live near u~1
// where error is amplified 1/t); outer log fast (bounded abs err ~4e-6).
__device__ __forceinline__ float gumbel32(uint2 key, uint32_t idx) {
  float f = uni01(rbits32(key, idx));
  float u = fmaxf(f, 1.17549435e-38f);
  float t = -logf(u);
  return -__logf(t);
}

struct BestPair { float v; int i; };

__device__ __forceinline__ void upd(BestPair& b, float v, int i) {
  if (v > b.v) { b.v = v; b.i = i; }
}

// Warp+block argmax (128 threads, tie-break min index), thread 0 holds result.
__device__ __forceinline__ BestPair block_argmax(BestPair best) {
  unsigned full = 0xffffffffu;
#pragma unroll
  for (int off = 16; off > 0; off >>= 1) {
    float ov = __shfl_down_sync(full, best.v, off);
    int   oi = __shfl_down_sync(full, best.i, off);
    if (ov > best.v || (ov == best.v && oi < best.i)) { best.v = ov; best.i = oi; }
  }
  __shared__ float sv[4];
  __shared__ int   si[4];
  int warp = threadIdx.x >> 5;
  int lane = threadIdx.x & 31;
  if (lane == 0) { sv[warp] = best.v; si[warp] = best.i; }
  __syncthreads();
  if (threadIdx.x == 0) {
#pragma unroll
    for (int w = 1; w < 4; w++) {
      if (sv[w] > best.v || (sv[w] == best.v && si[w] < best.i)) {
        best.v = sv[w]; best.i = si[w];
      }
    }
  }
  return best;
}

// ---------------- Kernel A: accept / accepted_num / emitted_num --------------------
__global__ void kSetup(const int* __restrict__ tok, const float* __restrict__ dp,
                       const float* __restrict__ vp, float* __restrict__ out,
                       int out_size) {
  int b = threadIdx.x;
  if (b >= kB) return;
  uint2 ku = threefry2x32(0u, 1u, 0u, 0u);   // split(key(1),3)[0]
  bool acc_arr[kN];
#pragma unroll
  for (int n = 0; n < kN; n++) {
    int L = b * kN + n;
    float u = uni01(rbits32(ku, (uint32_t)L));
    int t = tok[L];
    t = min(max(t, 0), kV - 1);
    float q = dp[(size_t)L * kV + t];
    float p = vp[((size_t)b * (kN + 1) + n) * kV + t];
    acc_arr[n] = (u * q < p);
  }
  int acc = 0, em = 0;
  bool alive = true;
#pragma unroll
  for (int n = 0; n < kN; n++) {
    acc += acc_arr[n] ? 1 : 0;
    if (alive) { if (acc_arr[n]) em++; else alive = false; }
  }
  if (out_size >= kB * (kN + 1) + 2 * kB) {
    out[kB * (kN + 1) + b] = (float)acc;
    out[kB * (kN + 1) + kB + b] = (float)em;
  }
  g_em[b] = em;
}

// ---------------- Mega kernel: bonus + recover argmax + final assembly -------------
// blocks [0, 1024):     bonus    (b = blk>>4, chunk = blk&15)
// blocks [1024, 2048):  recover
// Last block (ticket) combines partials in fixed order and writes tokens.
__global__ void kGumbel(const int* __restrict__ tok, const float* __restrict__ dp,
                        const float* __restrict__ vp, float* __restrict__ out) {
  int blk = blockIdx.x;
  bool is_bonus = blk < kBonusBlocks;
  int rb = is_bonus ? blk : blk - kBonusBlocks;
  int b = rb >> 4;
  int c = rb & (kCH - 1);
  int t = threadIdx.x;

  BestPair best = {neg_inf(), 0x7fffffff};

  if (is_bonus) {
    uint2 kb = threefry2x32(0u, 1u, 0u, 2u);  // subkey 2
    const float4* row = (const float4*)(vp + ((size_t)b * (kN + 1) + kN) * kV);
    uint32_t Lbase = (uint32_t)b * (uint32_t)kV;   // gumbel shape (B, V)
    for (int i = c * kQ4 + t; i < (c + 1) * kQ4; i += kTPB) {
      float4 p4 = row[i];
      int v = 4 * i;
      upd(best, __logf(p4.x + 1e-20f) + gumbel32(kb, Lbase + v + 0), v + 0);
      upd(best, __logf(p4.y + 1e-20f) + gumbel32(kb, Lbase + v + 1), v + 1);
      upd(best, __logf(p4.z + 1e-20f) + gumbel32(kb, Lbase + v + 2), v + 2);
      upd(best, __logf(p4.w + 1e-20f) + gumbel32(kb, Lbase + v + 3), v + 3);
    }
    best = block_argmax(best);
    if (t == 0) { g_bval[rb] = best.v; g_bidx[rb] = best.i; }
  } else {
    int em = g_em[b];
    if (em < kN) {
      // argmax(log(r/S'+eps)+G) == argmax(log(r+eps)+G): /S' is a monotone shift.
      uint2 kr = threefry2x32(0u, 1u, 0u, 1u);  // subkey 1
      const float4* drow = (const float4*)(dp + ((size_t)b * kN + em) * kV);
      const float4* vrow = (const float4*)(vp + ((size_t)b * (kN + 1) + em) * kV);
      uint32_t Lbase = (uint32_t)(b * kN + em) * (uint32_t)kV;  // shape (B, N, V)
      for (int i = c * kQ4 + t; i < (c + 1) * kQ4; i += kTPB) {
        float4 d4 = drow[i];
        float4 v4 = vrow[i];
        int v = 4 * i;
        upd(best, __logf(fmaxf(v4.x - d4.x, 0.0f) + 1e-20f) + gumbel32(kr, Lbase + v + 0), v + 0);
        upd(best, __logf(fmaxf(v4.y - d4.y, 0.0f) + 1e-20f) + gumbel32(kr, Lbase + v + 1), v + 1);
        upd(best, __logf(fmaxf(v4.z - d4.z, 0.0f) + 1e-20f) + gumbel32(kr, Lbase + v + 2), v + 2);
        upd(best, __logf(fmaxf(v4.w - d4.w, 0.0f) + 1e-20f) + gumbel32(kr, Lbase + v + 3), v + 3);
      }
      best = block_argmax(best);
      if (t == 0) { g_rval[rb] = best.v; g_ridx[rb] = best.i; }
    }
  }

  // ---- deterministic last-block final assembly -----------------------------------
  __threadfence();
  __shared__ bool amLast;
  if (t == 0) {
    unsigned tk = atomicAdd(&g_ticket, 1u);
    amLast = (tk == (unsigned)(kGridTotal - 1));
  }
  __syncthreads();
  if (!amLast) return;
  if (t == 0) g_ticket = 0;           // reset for next graph replay
  __threadfence();

  int bb = t;
  if (bb < kB) {
    volatile float* bval = g_bval;
    volatile int*   bidx = g_bidx;
    volatile float* rval = g_rval;
    volatile int*   ridx = g_ridx;
    float bv = neg_inf(); int bi = 0x7fffffff;
#pragma unroll
    for (int cc = 0; cc < kCH; cc++) {
      float v = bval[bb * kCH + cc]; int i = bidx[bb * kCH + cc];
      if (v > bv || (v == bv && i < bi)) { bv = v; bi = i; }
    }
    int em = g_em[bb];
    int fin = bi;
    if (em < kN) {
      float rv = neg_inf(); int ri = 0x7fffffff;
#pragma unroll
      for (int cc = 0; cc < kCH; cc++) {
        float v = rval[bb * kCH + cc]; int i = ridx[bb * kCH + cc];
        if (v > rv || (v == rv && i < ri)) { rv = v; ri = i; }
      }
      fin = ri;
    }
#pragma unroll
    for (int pos = 0; pos < kN + 1; pos++) {
      float o;
      if (pos < em)       o = (float)tok[bb * kN + pos];
      else if (pos == em) o = (float)fin;
      else                o = -1.0f;
      out[bb * (kN + 1) + pos] = o;
    }
  }
}

}  // namespace

extern "C" void kernel_launch(void* const* d_in, const int* in_sizes, int n_in,
                              void* d_out, int out_size) {
  const int*   tok = nullptr;
  const float* dp  = nullptr;
  const float* vp  = nullptr;
  for (int i = 0; i < n_in; i++) {
    if (in_sizes[i] == kB * kN)                      tok = (const int*)d_in[i];
    else if (in_sizes[i] == kB * kN * kV)            dp  = (const float*)d_in[i];
    else if (in_sizes[i] == kB * (kN + 1) * kV)      vp  = (const float*)d_in[i];
  }
  float* out = (float*)d_out;

  kSetup<<<1, kB>>>(tok, dp, vp, out, out_size);
  kGumbel<<<kGridTotal, kTPB>>>(tok, dp, vp, out);
}

// round 5
// speedup vs baseline: 2.1514x; 1.0343x over previous
#include <cuda_runtime.h>
#include <cstdint>

namespace {

constexpr int kB = 64;
constexpr int kN = 8;
constexpr int kV = 128000;
constexpr int kCH = 16;                 // chunks per row
constexpr int kQ4 = kV / kCH / 4;       // float4s per chunk = 2000
constexpr int kTPB = 128;
constexpr int kBonusBlocks = kB * kCH;        // 1024
constexpr int kGridTotal   = 2 * kB * kCH;    // 2048

__device__ float    g_bval[kB * kCH];
__device__ int      g_bidx[kB * kCH];
__device__ float    g_rval[kB * kCH];
__device__ int      g_ridx[kB * kCH];
__device__ unsigned g_ticket;

__device__ __forceinline__ float neg_inf() { return __int_as_float(0xff800000); }

// ---------------- JAX threefry2x32 (exact round structure) -------------------------
__device__ __forceinline__ void tfround(uint32_t& x0, uint32_t& x1, int r) {
  x0 += x1;
  x1 = __funnelshift_l(x1, x1, r);
  x1 ^= x0;
}

__device__ __forceinline__ uint2 threefry2x32(uint32_t k0, uint32_t k1,
                                              uint32_t x0, uint32_t x1) {
  uint32_t k2 = k0 ^ k1 ^ 0x1BD11BDAu;
  x0 += k0; x1 += k1;
  tfround(x0, x1, 13); tfround(x0, x1, 15); tfround(x0, x1, 26); tfround(x0, x1, 6);
  x0 += k1; x1 += k2 + 1u;
  tfround(x0, x1, 17); tfround(x0, x1, 29); tfround(x0, x1, 16); tfround(x0, x1, 24);
  x0 += k2; x1 += k0 + 2u;
  tfround(x0, x1, 13); tfround(x0, x1, 15); tfround(x0, x1, 26); tfround(x0, x1, 6);
  x0 += k0; x1 += k1 + 3u;
  tfround(x0, x1, 17); tfround(x0, x1, 29); tfround(x0, x1, 16); tfround(x0, x1, 24);
  x0 += k1; x1 += k2 + 4u;
  tfround(x0, x1, 13); tfround(x0, x1, 15); tfround(x0, x1, 26); tfround(x0, x1, 6);
  x0 += k2; x1 += k0 + 5u;
  return make_uint2(x0, x1);
}

__device__ __forceinline__ uint32_t rbits32(uint2 key, uint32_t idx) {
  uint2 o = threefry2x32(key.x, key.y, 0u, idx);
  return o.x ^ o.y;
}

__device__ __forceinline__ float uni01(uint32_t bits) {
  return __uint_as_float((bits >> 9) | 0x3f800000u) - 1.0f;
}

// t = -log(max(u, tiny)), accurate log (relative error matters for u near 1,
// which is exactly where argmax winners live).
__device__ __forceinline__ float tval(uint2 key, uint32_t idx) {
  float f = uni01(rbits32(key, idx));
  float u = fmaxf(f, 1.17549435e-38f);
  return -logf(u);
}

struct BestPair { float v; int i; };

__device__ __forceinline__ void upd(BestPair& b, float v, int i) {
  if (v > b.v) { b.v = v; b.i = i; }
}

// Warp+block argmax (128 threads, tie-break min index), thread 0 holds result.
__device__ __forceinline__ BestPair block_argmax(BestPair best) {
  unsigned full = 0xffffffffu;
#pragma unroll
  for (int off = 16; off > 0; off >>= 1) {
    float ov = __shfl_down_sync(full, best.v, off);
    int   oi = __shfl_down_sync(full, best.i, off);
    if (ov > best.v || (ov == best.v && oi < best.i)) { best.v = ov; best.i = oi; }
  }
  __shared__ float sv[4];
  __shared__ int   si[4];
  int warp = threadIdx.x >> 5;
  int lane = threadIdx.x & 31;
  if (lane == 0) { sv[warp] = best.v; si[warp] = best.i; }
  __syncthreads();
  if (threadIdx.x == 0) {
#pragma unroll
    for (int w = 1; w < 4; w++) {
      if (sv[w] > best.v || (sv[w] == best.v && si[w] < best.i)) {
        best.v = sv[w]; best.i = si[w];
      }
    }
  }
  return best;
}

// accept decision for (b, n) — shared by em computation everywhere
__device__ __forceinline__ bool accept_bn(int b, int n, const int* __restrict__ tok,
                                          const float* __restrict__ dp,
                                          const float* __restrict__ vp) {
  uint2 ku = threefry2x32(0u, 1u, 0u, 0u);   // split(key(1),3)[0] — const-folded
  int L = b * kN + n;
  float u = uni01(rbits32(ku, (uint32_t)L));
  int t = tok[L];
  t = min(max(t, 0), kV - 1);
  float q = dp[(size_t)L * kV + t];
  float p = vp[((size_t)b * (kN + 1) + n) * kV + t];
  return (u * q < p);
}

// ---------------- Single mega kernel ------------------------------------------------
// blocks [0, 1024):     bonus    (b = blk>>4, chunk = blk&15)
// blocks [1024, 2048):  recover  (self-computes em via lanes 0..7 ballot)
// Last block (ticket) combines partials, computes acc/em, writes all outputs.
__global__ void kGumbel(const int* __restrict__ tok, const float* __restrict__ dp,
                        const float* __restrict__ vp, float* __restrict__ out,
                        int out_size) {
  int blk = blockIdx.x;
  bool is_bonus = blk < kBonusBlocks;
  int rb = is_bonus ? blk : blk - kBonusBlocks;
  int b = rb >> 4;
  int c = rb & (kCH - 1);
  int t = threadIdx.x;

  BestPair best = {neg_inf(), 0x7fffffff};

  if (is_bonus) {
    uint2 kb = threefry2x32(0u, 1u, 0u, 2u);  // subkey 2 (const-folded)
    const float4* row = (const float4*)(vp + ((size_t)b * (kN + 1) + kN) * kV);
    uint32_t Lbase = (uint32_t)b * (uint32_t)kV;   // gumbel shape (B, V)
    for (int i = c * kQ4 + t; i < (c + 1) * kQ4; i += kTPB) {
      float4 p4 = row[i];
      int v = 4 * i;
      // maximize (p+eps)/t  ==  argmax log(p+eps) - log(t)  (monotone)
      upd(best, __fdividef(p4.x + 1e-20f, tval(kb, Lbase + v + 0)), v + 0);
      upd(best, __fdividef(p4.y + 1e-20f, tval(kb, Lbase + v + 1)), v + 1);
      upd(best, __fdividef(p4.z + 1e-20f, tval(kb, Lbase + v + 2)), v + 2);
      upd(best, __fdividef(p4.w + 1e-20f, tval(kb, Lbase + v + 3)), v + 3);
    }
    best = block_argmax(best);
    if (t == 0) { g_bval[rb] = best.v; g_bidx[rb] = best.i; }
  } else {
    // self-compute em for batch b: lanes 0..7 of warp 0 + ballot
    __shared__ int s_em;
    if (t < 8) {
      bool acc = accept_bn(b, t, tok, dp, vp);
      unsigned m = __ballot_sync(0xffu, acc);
      if (t == 0) s_em = __ffs((~m) & 0x1FF) - 1;   // trailing-ones count, 8 if all
    }
    __syncthreads();
    int em = s_em;
    if (em < kN) {
      // argmax(log(r/S'+eps)+G) == argmax((r+eps)/t): /S' monotone shift, log monotone.
      uint2 kr = threefry2x32(0u, 1u, 0u, 1u);  // subkey 1 (const-folded)
      const float4* drow = (const float4*)(dp + ((size_t)b * kN + em) * kV);
      const float4* vrow = (const float4*)(vp + ((size_t)b * (kN + 1) + em) * kV);
      uint32_t Lbase = (uint32_t)(b * kN + em) * (uint32_t)kV;  // shape (B, N, V)
      for (int i = c * kQ4 + t; i < (c + 1) * kQ4; i += kTPB) {
        float4 d4 = drow[i];
        float4 v4 = vrow[i];
        int v = 4 * i;
        upd(best, __fdividef(fmaxf(v4.x - d4.x, 0.0f) + 1e-20f, tval(kr, Lbase + v + 0)), v + 0);
        upd(best, __fdividef(fmaxf(v4.y - d4.y, 0.0f) + 1e-20f, tval(kr, Lbase + v + 1)), v + 1);
        upd(best, __fdividef(fmaxf(v4.z - d4.z, 0.0f) + 1e-20f, tval(kr, Lbase + v + 2)), v + 2);
        upd(best, __fdividef(fmaxf(v4.w - d4.w, 0.0f) + 1e-20f, tval(kr, Lbase + v + 3)), v + 3);
      }
      best = block_argmax(best);
      if (t == 0) { g_rval[rb] = best.v; g_ridx[rb] = best.i; }
    }
  }

  // ---- deterministic last-block final assembly -----------------------------------
  __threadfence();
  __shared__ bool amLast;
  if (t == 0) {
    unsigned tk = atomicAdd(&g_ticket, 1u);
    amLast = (tk == (unsigned)(kGridTotal - 1));
  }
  __syncthreads();
  if (!amLast) return;
  if (t == 0) g_ticket = 0;           // reset for next graph replay
  __threadfence();

  int bb = t;
  if (bb < kB) {
    // accepted / emitted counts
    int acc = 0, em = 0;
    bool alive = true;
#pragma unroll
    for (int n = 0; n < kN; n++) {
      bool a = accept_bn(bb, n, tok, dp, vp);
      acc += a ? 1 : 0;
      if (alive) { if (a) em++; else alive = false; }
    }
    if (out_size >= kB * (kN + 1) + 2 * kB) {
      out[kB * (kN + 1) + bb] = (float)acc;
      out[kB * (kN + 1) + kB + bb] = (float)em;
    }

    volatile float* bval = g_bval;
    volatile int*   bidx = g_bidx;
    volatile float* rval = g_rval;
    volatile int*   ridx = g_ridx;
    float bv = neg_inf(); int bi = 0x7fffffff;
#pragma unroll
    for (int cc = 0; cc < kCH; cc++) {
      float v = bval[bb * kCH + cc]; int i = bidx[bb * kCH + cc];
      if (v > bv || (v == bv && i < bi)) { bv = v; bi = i; }
    }
    int fin = bi;
    if (em < kN) {
      float rv = neg_inf(); int ri = 0x7fffffff;
#pragma unroll
      for (int cc = 0; cc < kCH; cc++) {
        float v = rval[bb * kCH + cc]; int i = ridx[bb * kCH + cc];
        if (v > rv || (v == rv && i < ri)) { rv = v; ri = i; }
      }
      fin = ri;
    }
#pragma unroll
    for (int pos = 0; pos < kN + 1; pos++) {
      float o;
      if (pos < em)       o = (float)tok[bb * kN + pos];
      else if (pos == em) o = (float)fin;
      else                o = -1.0f;
      out[bb * (kN + 1) + pos] = o;
    }
  }
}

}  // namespace

extern "C" void kernel_launch(void* const* d_in, const int* in_sizes, int n_in,
                              void* d_out, int out_size) {
  const int*   tok = nullptr;
  const float* dp  = nullptr;
  const float* vp  = nullptr;
  for (int i = 0; i < n_in; i++) {
    if (in_sizes[i] == kB * kN)                      tok = (const int*)d_in[i];
    else if (in_sizes[i] == kB * kN * kV)            dp  = (const float*)d_in[i];
    else if (in_sizes[i] == kB * (kN + 1) * kV)      vp  = (const float*)d_in[i];
  }
  float* out = (float*)d_out;

  kGumbel<<<kGridTotal, kTPB>>>(tok, dp, vp, out, out_size);
}